// round 12
// baseline (speedup 1.0000x reference)
#include <cuda_runtime.h>
#include <cooperative_groups.h>
namespace cg = cooperative_groups;

// Problem constants (fixed by the reference)
#define Bn 32
#define Nn 1024
#define Fn 128
#define Dn 128
#define SL 16                       // k1 slices per batch
#define RPB 64                      // rows per k1 slice block
#define CS3 8                       // k3 cluster size (blocks per batch)
#define RPC3 128                    // rows per k3 block
#define SCALE 0.08838834764831843f  // 128^-0.5

// Scratch (static __device__ — no allocation allowed)
__device__ float g_XsumP[Bn][SL][Fn];
__device__ float g_u[Bn][Fn];
__device__ float g_c[Bn];

// ---------------------------------------------------------------------------
// K1: column-sum partials of X. grid (B, SL) x 256. Triggers at entry.
__global__ __launch_bounds__(256, 4)
void k1(const float* __restrict__ X) {
    cudaTriggerProgrammaticLaunchCompletion();
    int b = blockIdx.x, s = blockIdx.y, t = threadIdx.x;
    int w = t >> 5, lane = t & 31;
    __shared__ float4 shP[8][32];
    const float4* Xr = (const float4*)(X + ((size_t)b * Nn + s * RPB + w * 8) * Fn);
    float4 cs = Xr[lane];
    #pragma unroll
    for (int r = 1; r < 8; r++) {
        float4 xx = Xr[(size_t)r * 32 + lane];
        cs.x += xx.x; cs.y += xx.y; cs.z += xx.z; cs.w += xx.w;
    }
    shP[w][lane] = cs;
    __syncthreads();
    if (t < 32) {
        float4 sum = shP[0][t];
        #pragma unroll
        for (int g = 1; g < 8; g++) {
            float4 p = shP[g][t];
            sum.x += p.x; sum.y += p.y; sum.z += p.z; sum.w += p.w;
        }
        ((float4*)g_XsumP[b][s])[t] = sum;
    }
}

// ---------------------------------------------------------------------------
// K2: ksum -> u, c. grid B x 256. Triggers at entry (k3 launches during k1).
// Prefetches Wk+Wq into dynamic smem before its dependency sync.
__global__ __launch_bounds__(256)
void k2(const float* __restrict__ Wq, const float* __restrict__ bq,
        const float* __restrict__ Wk, const float* __restrict__ bk) {
    cudaTriggerProgrammaticLaunchCompletion();
    extern __shared__ float dyn[];
    float* sWk = dyn;                 // [128*128]
    float* sWq = dyn + Fn * Dn;       // [128*129] padded rows
    int b = blockIdx.x, t = threadIdx.x;
    int w = t >> 5, lane = t & 31;
    __shared__ float Xs[Fn], Ks[Fn], part[2][Fn], red8[8];

    {
        const float4* Wk4 = (const float4*)Wk;
        float4* sWk4 = (float4*)sWk;
        #pragma unroll
        for (int i = 0; i < 16; i++) sWk4[t + i * 256] = Wk4[t + i * 256];
        const float4* Wq4 = (const float4*)Wq;
        #pragma unroll
        for (int i = 0; i < 16; i++) {
            float4 v = Wq4[t + i * 256];
            int idx = (t + i * 256) * 4;
            int row = idx >> 7, col = idx & 127;
            float* p = sWq + row * 129 + col;
            p[0] = v.x; p[1] = v.y; p[2] = v.z; p[3] = v.w;
        }
    }
    cudaGridDependencySynchronize();
    __syncthreads();

    if (t < 128) {
        float s0 = 0.f, s1 = 0.f, s2 = 0.f, s3 = 0.f;
        #pragma unroll
        for (int j = 0; j < SL; j += 4) {
            s0 += g_XsumP[b][j][t];
            s1 += g_XsumP[b][j + 1][t];
            s2 += g_XsumP[b][j + 2][t];
            s3 += g_XsumP[b][j + 3][t];
        }
        Xs[t] = (s0 + s1) + (s2 + s3);
    }
    __syncthreads();
    int d = t & 127, h = t >> 7;
    {
        const float* wk = sWk + (h * 64) * Dn + d;
        float a0 = 0.f, a1 = 0.f, a2 = 0.f, a3 = 0.f;
        #pragma unroll
        for (int f = 0; f < 64; f += 4) {
            a0 += Xs[h * 64 + f]     * wk[(f)     * Dn];
            a1 += Xs[h * 64 + f + 1] * wk[(f + 1) * Dn];
            a2 += Xs[h * 64 + f + 2] * wk[(f + 2) * Dn];
            a3 += Xs[h * 64 + f + 3] * wk[(f + 3) * Dn];
        }
        part[h][d] = (a0 + a1) + (a2 + a3);
    }
    __syncthreads();
    if (t < 128) Ks[t] = part[0][t] + part[1][t] + (float)Nn * bk[t];
    __syncthreads();
    {
        const float* wq = sWq + d * 129 + h * 64;
        float a0 = 0.f, a1 = 0.f, a2 = 0.f, a3 = 0.f;
        #pragma unroll
        for (int f = 0; f < 64; f += 4) {
            a0 += wq[f]     * Ks[h * 64 + f];
            a1 += wq[f + 1] * Ks[h * 64 + f + 1];
            a2 += wq[f + 2] * Ks[h * 64 + f + 2];
            a3 += wq[f + 3] * Ks[h * 64 + f + 3];
        }
        part[h][d] = (a0 + a1) + (a2 + a3);
    }
    __syncthreads();
    if (t < 128) g_u[b][t] = part[0][t] + part[1][t];
    float rv = (t < 128) ? bq[t] * Ks[t] : 0.f;
    #pragma unroll
    for (int off = 16; off > 0; off >>= 1)
        rv += __shfl_xor_sync(0xffffffffu, rv, off);
    if (lane == 0) red8[w] = rv;
    __syncthreads();
    if (t == 0)
        g_c[b] = ((red8[0] + red8[1]) + (red8[2] + red8[3]));
}

// ---------------------------------------------------------------------------
// K3F: fused agg + softmax partials + cluster finalize.
// grid 256 x 256, cluster of 8 = one batch. 16 rows/warp (2 groups of 8).
// X/mask prefetched before the dependency sync; rank0 prefetches Wv.
// After ONE cluster.sync: every block writes its attn rows from smem;
// rank0 gathers peer acc via DSMEM and writes context.
__global__ __launch_bounds__(256, 2) __cluster_dims__(CS3, 1, 1)
void k3f(const float* __restrict__ X, const float* __restrict__ mask,
         const float* __restrict__ Wv, const float* __restrict__ bv,
         float* __restrict__ attn, float* __restrict__ ctx) {
    extern __shared__ float sWv[];               // [128*128] (rank0 only uses)
    cg::cluster_group cluster = cg::this_cluster();
    int t = threadIdx.x, w = t >> 5, lane = t & 31;
    int bid = blockIdx.x;
    int b = bid >> 3, rank = bid & 7;
    int rowC = rank * RPC3;
    int rowW = rowC + w * 16;

    __shared__ float shU[Fn];
    __shared__ float shAgg[RPC3];
    __shared__ float shAcc[Fn];
    __shared__ float shMw[8], shSw[8];
    __shared__ float4 shP[8][32];
    __shared__ float shMS[2];                    // block Mx, Sx
    __shared__ float Mall[CS3], Sall[CS3];
    __shared__ float shY[Fn], partv[2][Fn];

    // ---- prologue: issue independent loads before the dependency sync ----
    const float4* Xr = (const float4*)(X + ((size_t)b * Nn + rowW) * Fn);
    float4 x0[8], x1[8];
    #pragma unroll
    for (int r = 0; r < 8; r++) x0[r] = Xr[(size_t)r * 32 + lane];
    #pragma unroll
    for (int r = 0; r < 8; r++) x1[r] = Xr[(size_t)(8 + r) * 32 + lane];
    float mv = (lane < 16) ? mask[b * Nn + rowW + lane] : 0.f;

    if (rank == 0) {                             // Wv prefetch overlaps k1/k2
        const float4* Wv4 = (const float4*)Wv;
        float4* sWv4 = (float4*)sWv;
        #pragma unroll
        for (int j = 0; j < 16; j++) sWv4[t + j * 256] = Wv4[t + j * 256];
    }

    cudaGridDependencySynchronize();             // wait for k2

    if (t < 128) shU[t] = g_u[b][t];
    __syncthreads();
    float c = g_c[b];
    float4 uv = ((float4*)shU)[lane];

    // ---- group 0 (rows rowW..rowW+7) ----
    float Mw, Sw;
    float4 accw;
    {
        float d[8];
        #pragma unroll
        for (int r = 0; r < 8; r++)
            d[r] = x0[r].x * uv.x + x0[r].y * uv.y + x0[r].z * uv.z + x0[r].w * uv.w;
        #pragma unroll
        for (int off = 16; off > 0; off >>= 1) {
            #pragma unroll
            for (int r = 0; r < 8; r++)
                d[r] += __shfl_xor_sync(0xffffffffu, d[r], off);
        }
        float a[8];
        #pragma unroll
        for (int r = 0; r < 8; r++) {
            float mval = __shfl_sync(0xffffffffu, mv, r);
            a[r] = (mval != 0.f) ? SCALE * (d[r] + c) : -1e9f;
        }
        float myA = a[0];
        #pragma unroll
        for (int r = 1; r < 8; r++) if (lane == r) myA = a[r];
        if (lane < 8) shAgg[w * 16 + lane] = myA;

        float M8 = a[0];
        #pragma unroll
        for (int r = 1; r < 8; r++) M8 = fmaxf(M8, a[r]);
        float ev[8], S8 = 0.f;
        #pragma unroll
        for (int r = 0; r < 8; r++) { ev[r] = __expf(a[r] - M8); S8 += ev[r]; }
        float4 a8 = make_float4(0.f, 0.f, 0.f, 0.f);
        #pragma unroll
        for (int r = 0; r < 8; r++) {
            a8.x += ev[r] * x0[r].x; a8.y += ev[r] * x0[r].y;
            a8.z += ev[r] * x0[r].z; a8.w += ev[r] * x0[r].w;
        }
        Mw = M8; Sw = S8; accw = a8;
    }
    // ---- group 1 (rows rowW+8..rowW+15) ----
    {
        float d[8];
        #pragma unroll
        for (int r = 0; r < 8; r++)
            d[r] = x1[r].x * uv.x + x1[r].y * uv.y + x1[r].z * uv.z + x1[r].w * uv.w;
        #pragma unroll
        for (int off = 16; off > 0; off >>= 1) {
            #pragma unroll
            for (int r = 0; r < 8; r++)
                d[r] += __shfl_xor_sync(0xffffffffu, d[r], off);
        }
        float a[8];
        #pragma unroll
        for (int r = 0; r < 8; r++) {
            float mval = __shfl_sync(0xffffffffu, mv, 8 + r);
            a[r] = (mval != 0.f) ? SCALE * (d[r] + c) : -1e9f;
        }
        float myA = a[0];
        #pragma unroll
        for (int r = 1; r < 8; r++) if (lane == r) myA = a[r];
        if (lane < 8) shAgg[w * 16 + 8 + lane] = myA;

        float M8 = a[0];
        #pragma unroll
        for (int r = 1; r < 8; r++) M8 = fmaxf(M8, a[r]);
        float ev[8], S8 = 0.f;
        #pragma unroll
        for (int r = 0; r < 8; r++) { ev[r] = __expf(a[r] - M8); S8 += ev[r]; }
        float4 a8 = make_float4(0.f, 0.f, 0.f, 0.f);
        #pragma unroll
        for (int r = 0; r < 8; r++) {
            a8.x += ev[r] * x1[r].x; a8.y += ev[r] * x1[r].y;
            a8.z += ev[r] * x1[r].z; a8.w += ev[r] * x1[r].w;
        }
        float nM = fmaxf(Mw, M8);
        float s0 = __expf(Mw - nM), s1 = __expf(M8 - nM);
        Sw = Sw * s0 + S8 * s1;
        accw.x = accw.x * s0 + a8.x * s1;
        accw.y = accw.y * s0 + a8.y * s1;
        accw.z = accw.z * s0 + a8.z * s1;
        accw.w = accw.w * s0 + a8.w * s1;
        Mw = nM;
    }

    // ---- block merge of 8 warp partials ----
    if (lane == 0) { shMw[w] = Mw; shSw[w] = Sw; }
    shP[w][lane] = accw;
    __syncthreads();
    if (t < 32) {
        float bMb = shMw[0];
        #pragma unroll
        for (int j = 1; j < 8; j++) bMb = fmaxf(bMb, shMw[j]);
        float Sb = 0.f;
        float4 ya = make_float4(0.f, 0.f, 0.f, 0.f);
        #pragma unroll
        for (int j = 0; j < 8; j++) {
            float f = __expf(shMw[j] - bMb);
            Sb += f * shSw[j];
            float4 p = shP[j][t];
            ya.x += f * p.x; ya.y += f * p.y; ya.z += f * p.z; ya.w += f * p.w;
        }
        ((float4*)shAcc)[t] = ya;
        if (t == 0) { shMS[0] = bMb; shMS[1] = Sb; }
    }
    __syncthreads();

    // ---- cluster merge: one sync, then DSMEM gathers ----
    cluster.sync();

    if (t < CS3) {
        const float* pMS = (const float*)cluster.map_shared_rank(shMS, t);
        Mall[t] = pMS[0];
        Sall[t] = pMS[1];
    }
    __syncthreads();
    float bM = Mall[0];
    #pragma unroll
    for (int j = 1; j < CS3; j++) bM = fmaxf(bM, Mall[j]);
    float Z = 0.f;
    #pragma unroll
    for (int j = 0; j < CS3; j++) Z += __expf(Mall[j] - bM) * Sall[j];
    float invZ = 1.0f / Z;

    // attn for this block's 128 rows, straight from smem
    if (t < 128)
        attn[b * Nn + rowC + t] = __expf(shAgg[t] - bM) * invZ;

    // rank0: gather peer acc partials (DSMEM), before releasing peers
    if (rank == 0 && t < 128) {
        float y = 0.f;
        #pragma unroll
        for (int r = 0; r < CS3; r++) {
            const float* pa = (const float*)cluster.map_shared_rank(shAcc, r);
            y += __expf(Mall[r] - bM) * pa[t];
        }
        shY[t] = y * invZ;
    }
    cluster.sync();                              // peers' smem alive until here

    if (rank == 0) {
        int d = t & 127, h = t >> 7;
        const float* wv = sWv + (h * 64) * Dn + d;
        float a0 = 0.f, a1 = 0.f, a2 = 0.f, a3 = 0.f;
        #pragma unroll
        for (int f = 0; f < 64; f += 4) {
            a0 += shY[h * 64 + f]     * wv[(f)     * Dn];
            a1 += shY[h * 64 + f + 1] * wv[(f + 1) * Dn];
            a2 += shY[h * 64 + f + 2] * wv[(f + 2) * Dn];
            a3 += shY[h * 64 + f + 3] * wv[(f + 3) * Dn];
        }
        partv[h][d] = (a0 + a1) + (a2 + a3);
        __syncthreads();
        if (t < 128)
            ctx[b * Dn + t] = bv[t] + partv[0][t] + partv[1][t];
    }
}

// ---------------------------------------------------------------------------
extern "C" void kernel_launch(void* const* d_in, const int* in_sizes, int n_in,
                              void* d_out, int out_size) {
    const float* X    = (const float*)d_in[0];
    const float* mask = (const float*)d_in[1];
    const float* Wq   = (const float*)d_in[2];
    const float* bq   = (const float*)d_in[3];
    const float* Wk   = (const float*)d_in[4];
    const float* bk   = (const float*)d_in[5];
    const float* Wv   = (const float*)d_in[6];
    const float* bv   = (const float*)d_in[7];
    float* out  = (float*)d_out;
    float* attn = out;              // [B,N,1]
    float* ctx  = out + Bn * Nn;    // [B,D]

    const int k2smem = (Fn * Dn + Fn * 129) * (int)sizeof(float);   // 131584
    const int k3smem = Fn * Dn * (int)sizeof(float);                // 65536
    static bool attrSet = false;
    if (!attrSet) {
        cudaFuncSetAttribute(k2, cudaFuncAttributeMaxDynamicSharedMemorySize, k2smem);
        cudaFuncSetAttribute(k3f, cudaFuncAttributeMaxDynamicSharedMemorySize, k3smem);
        attrSet = true;
    }

    cudaLaunchAttribute pdlAttr;
    pdlAttr.id = cudaLaunchAttributeProgrammaticStreamSerialization;
    pdlAttr.val.programmaticStreamSerializationAllowed = 1;

    {   // k1 (triggers at entry)
        cudaLaunchConfig_t cfg = {};
        cfg.gridDim = dim3(Bn, SL); cfg.blockDim = dim3(256);
        cfg.stream = 0;
        cudaLaunchKernelEx(&cfg, k1, X);
    }
    {   // k2: PDL on k1; triggers at entry
        cudaLaunchConfig_t cfg = {};
        cfg.gridDim = dim3(Bn); cfg.blockDim = dim3(256);
        cfg.dynamicSmemBytes = k2smem;
        cfg.stream = 0; cfg.attrs = &pdlAttr; cfg.numAttrs = 1;
        cudaLaunchKernelEx(&cfg, k2, Wq, bq, Wk, bk);
    }
    {   // k3f: PDL on k2; clusters of 8 (one batch each)
        cudaLaunchConfig_t cfg = {};
        cfg.gridDim = dim3(Bn * CS3); cfg.blockDim = dim3(256);
        cfg.dynamicSmemBytes = k3smem;
        cfg.stream = 0; cfg.attrs = &pdlAttr; cfg.numAttrs = 1;
        cudaLaunchKernelEx(&cfg, k3f, X, mask, Wv, bv, attn, ctx);
    }
}

// round 13
// speedup vs baseline: 1.1555x; 1.1555x over previous
#include <cuda_runtime.h>
#include <cooperative_groups.h>
#include <cstdint>
namespace cg = cooperative_groups;

// Problem constants (fixed by the reference)
#define Bn 32
#define Nn 1024
#define Fn 128
#define Dn 128
#define CS 8                        // cluster size = CTAs per batch
#define RPC 128                     // rows per CTA
#define SCALE 0.08838834764831843f  // 128^-0.5
#define XT_BYTES (RPC * Fn * 4)     // 65536

__device__ __forceinline__ uint32_t smem_u32(const void* p) {
    return (uint32_t)__cvta_generic_to_shared(p);
}

__global__ __launch_bounds__(256, 2) __cluster_dims__(CS, 1, 1)
void ga(const float* __restrict__ X, const float* __restrict__ mask,
        const float* __restrict__ Wq, const float* __restrict__ bq,
        const float* __restrict__ Wk, const float* __restrict__ bk,
        const float* __restrict__ Wv, const float* __restrict__ bv,
        float* __restrict__ attn, float* __restrict__ ctx) {
    extern __shared__ float dyn[];
    float* Xt  = dyn;                 // [128][128]  X tile (rows rowC..rowC+127)
    float* sWk = dyn + Fn * Fn;       // [128][17]   Wk[:, dBase..dBase+16)
    float* sWq = sWk + Fn * 17;       // [128][17]   Wq[dBase+i][:] as [d?]  see below
    float* sWv = sWq + Fn * 17;       // [128][17]   Wv[:, dBase..dBase+16)
    // sWq stores Wq[d][fBase+i] for ALL d (128) and i<16 where fBase=rank*16:
    // used for u_part[d] = sum_i Wq[d][fBase+i] * ksl[i]

    __shared__ __align__(16) float shXs[Fn];    // this block's colsum partial
    __shared__ float shXsF[Fn];                 // full Xsum (gathered)
    __shared__ float shKsl[16];                 // ksum slice (d in my 16-slice)
    __shared__ float shUp[Fn];                  // u partial over my f-slice
    __shared__ float shUF[Fn];                  // full u (gathered+summed)
    __shared__ float shAgg[RPC];
    __shared__ __align__(16) float shAcc[Fn];
    __shared__ float shY[Fn];
    __shared__ float shMask[RPC];
    __shared__ float shBk[16], shBq[16], shBv[16];
    __shared__ float prt[16][16];               // seg x d partials (ksum, ctx)
    __shared__ float prt2[2][Fn];               // u_part partials
    __shared__ float4 shP[8][32];
    __shared__ float shMw[8], shSw[8];
    __shared__ float shMS[2];                   // block M, S
    __shared__ float Mall[CS], Sall[CS];
    __shared__ float cLoc, cFull;
    __shared__ __align__(8) unsigned long long mbar;

    cg::cluster_group cluster = cg::this_cluster();
    int t = threadIdx.x, w = t >> 5, lane = t & 31;
    int bid = blockIdx.x, b = bid >> 3, rank = bid & 7;
    int rowC = rank * RPC;
    int dBase = rank * 16;

    uint32_t mb = smem_u32(&mbar);
    uint32_t xt = smem_u32(Xt);

    // ---- prologue: mbarrier + bulk X copy, then LDG weight slices ----------
    if (t == 0)
        asm volatile("mbarrier.init.shared.b64 [%0], 1;" :: "r"(mb) : "memory");
    __syncthreads();
    if (t == 0) {
        asm volatile("mbarrier.arrive.expect_tx.shared.b64 _, [%0], %1;"
                     :: "r"(mb), "r"((uint32_t)XT_BYTES) : "memory");
        const float* src = X + ((size_t)b * Nn + rowC) * Fn;   // contiguous 64KB
        asm volatile(
            "cp.async.bulk.shared::cluster.global.mbarrier::complete_tx::bytes "
            "[%0], [%1], %2, [%3];"
            :: "r"(xt), "l"(src), "r"((uint32_t)XT_BYTES), "r"(mb) : "memory");
    }

    // weight slices (independent of X): 128 rows x 16 cols each, stride 17
    {
        int f = t >> 1, hh = (t & 1) * 8;
        float4 v0 = *(const float4*)(Wk + (size_t)f * Dn + dBase + hh);
        float4 v1 = *(const float4*)(Wk + (size_t)f * Dn + dBase + hh + 4);
        float* p = sWk + f * 17 + hh;
        p[0]=v0.x; p[1]=v0.y; p[2]=v0.z; p[3]=v0.w;
        p[4]=v1.x; p[5]=v1.y; p[6]=v1.z; p[7]=v1.w;
        // sWq: Wq[d][dBase..]: u_part needs Wq[d][fslice] where fslice = rank*16
        v0 = *(const float4*)(Wq + (size_t)f * Dn + dBase + hh);
        v1 = *(const float4*)(Wq + (size_t)f * Dn + dBase + hh + 4);
        p = sWq + f * 17 + hh;
        p[0]=v0.x; p[1]=v0.y; p[2]=v0.z; p[3]=v0.w;
        p[4]=v1.x; p[5]=v1.y; p[6]=v1.z; p[7]=v1.w;
        v0 = *(const float4*)(Wv + (size_t)f * Dn + dBase + hh);
        v1 = *(const float4*)(Wv + (size_t)f * Dn + dBase + hh + 4);
        p = sWv + f * 17 + hh;
        p[0]=v0.x; p[1]=v0.y; p[2]=v0.z; p[3]=v0.w;
        p[4]=v1.x; p[5]=v1.y; p[6]=v1.z; p[7]=v1.w;
    }
    if (t < 128) shMask[t] = mask[b * Nn + rowC + t];
    if (t < 16) { shBk[t] = bk[dBase + t]; shBq[t] = bq[dBase + t]; shBv[t] = bv[dBase + t]; }
    __syncthreads();

    // wait for X tile
    {
        unsigned done = 0;
        while (!done) {
            asm volatile(
                "{\n\t.reg .pred p;\n\t"
                "mbarrier.try_wait.parity.shared.b64 p, [%1], %2;\n\t"
                "selp.b32 %0, 1, 0, p;\n\t}"
                : "=r"(done) : "r"(mb), "r"(0u) : "memory");
        }
    }
    __syncthreads();

    // ---- Phase A: column-sum partial over this block's 128 rows ------------
    {
        const float4* X4 = (const float4*)Xt;
        int r0 = w * 16;
        float4 cs = X4[(size_t)r0 * 32 + lane];
        #pragma unroll
        for (int r = 1; r < 16; r++) {
            float4 xx = X4[(size_t)(r0 + r) * 32 + lane];
            cs.x += xx.x; cs.y += xx.y; cs.z += xx.z; cs.w += xx.w;
        }
        shP[w][lane] = cs;
    }
    __syncthreads();
    if (t < 32) {
        float4 sum = shP[0][t];
        #pragma unroll
        for (int g = 1; g < 8; g++) {
            float4 p = shP[g][t];
            sum.x += p.x; sum.y += p.y; sum.z += p.z; sum.w += p.w;
        }
        ((float4*)shXs)[t] = sum;
    }
    __syncthreads();
    cluster.sync();                                           // #1

    // ---- Phase B1: gather Xsum; ksum slice; c_local; u partial --------------
    if (t < 128) {
        float s = 0.f;
        #pragma unroll
        for (int r = 0; r < CS; r++) {
            const float* p = (const float*)cluster.map_shared_rank(shXs, r);
            s += p[t];
        }
        shXsF[t] = s;
    }
    __syncthreads();
    {   // ksum slice: d in [dBase, dBase+16)
        int d = t & 15, seg = t >> 4;
        float a = 0.f;
        #pragma unroll
        for (int j = 0; j < 8; j++) {
            int f = seg * 8 + j;
            a += shXsF[f] * sWk[f * 17 + d];
        }
        prt[seg][d] = a;
    }
    __syncthreads();
    if (t < 16) {
        float a = 0.f;
        #pragma unroll
        for (int s = 0; s < 16; s++) a += prt[s][t];
        shKsl[t] = a + (float)Nn * shBk[t];
    }
    __syncthreads();
    {   // c_local = sum_i bq[dBase+i] * ksl[i]
        float v = (t < 16) ? shBq[t] * shKsl[t] : 0.f;
        if (w == 0) {
            #pragma unroll
            for (int off = 8; off > 0; off >>= 1)
                v += __shfl_xor_sync(0xffffffffu, v, off);
            if (lane == 0) cLoc = v;
        }
    }
    {   // u partial: up[d] = sum_i Wq[d][dBase+i] * ksl[i], all d
        int d = t & 127, h = t >> 7;
        float a = 0.f;
        #pragma unroll
        for (int j = 0; j < 8; j++) {
            int i = h * 8 + j;
            a += sWq[d * 17 + i] * shKsl[i];
        }
        prt2[h][d] = a;
    }
    __syncthreads();
    if (t < 128) shUp[t] = prt2[0][t] + prt2[1][t];
    __syncthreads();
    cluster.sync();                                           // #2

    // ---- Phase B2: gather full u and c --------------------------------------
    if (t < 128) {
        float s = 0.f;
        #pragma unroll
        for (int r = 0; r < CS; r++) {
            const float* p = (const float*)cluster.map_shared_rank(shUp, r);
            s += p[t];
        }
        shUF[t] = s;
    }
    {
        float cv = 0.f;
        if (w == 0 && lane < CS)
            cv = *(const float*)cluster.map_shared_rank(&cLoc, lane);
        if (w == 0) {
            #pragma unroll
            for (int off = 4; off > 0; off >>= 1)
                cv += __shfl_xor_sync(0xffffffffu, cv, off);
            if (lane == 0) cFull = cv;
        }
    }
    __syncthreads();

    // ---- Phase C: agg + softmax partials from smem X ------------------------
    {
        float c = cFull;
        float4 uv = ((const float4*)shUF)[lane];
        const float4* X4 = (const float4*)Xt;
        int rw = w * 16;

        float Mw = -3.0e38f, Sw = 0.f;
        float4 accw = make_float4(0.f, 0.f, 0.f, 0.f);
        #pragma unroll
        for (int g = 0; g < 2; g++) {
            float4 x[8];
            float d[8];
            #pragma unroll
            for (int r = 0; r < 8; r++) {
                x[r] = X4[(size_t)(rw + g * 8 + r) * 32 + lane];
                d[r] = x[r].x * uv.x + x[r].y * uv.y + x[r].z * uv.z + x[r].w * uv.w;
            }
            #pragma unroll
            for (int off = 16; off > 0; off >>= 1) {
                #pragma unroll
                for (int r = 0; r < 8; r++)
                    d[r] += __shfl_xor_sync(0xffffffffu, d[r], off);
            }
            float a[8];
            #pragma unroll
            for (int r = 0; r < 8; r++)
                a[r] = (shMask[rw + g * 8 + r] != 0.f) ? SCALE * (d[r] + c) : -1e9f;

            float myA = a[0];
            #pragma unroll
            for (int r = 1; r < 8; r++) if (lane == r) myA = a[r];
            if (lane < 8) shAgg[rw + g * 8 + lane] = myA;

            float M8 = a[0];
            #pragma unroll
            for (int r = 1; r < 8; r++) M8 = fmaxf(M8, a[r]);
            float ev[8], S8 = 0.f;
            #pragma unroll
            for (int r = 0; r < 8; r++) { ev[r] = __expf(a[r] - M8); S8 += ev[r]; }
            float4 a8 = make_float4(0.f, 0.f, 0.f, 0.f);
            #pragma unroll
            for (int r = 0; r < 8; r++) {
                a8.x += ev[r] * x[r].x; a8.y += ev[r] * x[r].y;
                a8.z += ev[r] * x[r].z; a8.w += ev[r] * x[r].w;
            }
            float nM = fmaxf(Mw, M8);
            float s0 = __expf(Mw - nM), s1 = __expf(M8 - nM);
            Sw = Sw * s0 + S8 * s1;
            accw.x = accw.x * s0 + a8.x * s1;
            accw.y = accw.y * s0 + a8.y * s1;
            accw.z = accw.z * s0 + a8.z * s1;
            accw.w = accw.w * s0 + a8.w * s1;
            Mw = nM;
        }
        if (lane == 0) { shMw[w] = Mw; shSw[w] = Sw; }
        shP[w][lane] = accw;
    }
    __syncthreads();
    if (t < 32) {
        float bMb = shMw[0];
        #pragma unroll
        for (int j = 1; j < 8; j++) bMb = fmaxf(bMb, shMw[j]);
        float Sb = 0.f;
        float4 ya = make_float4(0.f, 0.f, 0.f, 0.f);
        #pragma unroll
        for (int j = 0; j < 8; j++) {
            float f = __expf(shMw[j] - bMb);
            Sb += f * shSw[j];
            float4 p = shP[j][t];
            ya.x += f * p.x; ya.y += f * p.y; ya.z += f * p.z; ya.w += f * p.w;
        }
        ((float4*)shAcc)[t] = ya;
        if (t == 0) { shMS[0] = bMb; shMS[1] = Sb; }
    }
    __syncthreads();
    cluster.sync();                                           // #3

    // ---- Phase D: cluster merge, attn, y gather ------------------------------
    if (t < CS) {
        const float* pMS = (const float*)cluster.map_shared_rank(shMS, t);
        Mall[t] = pMS[0];
        Sall[t] = pMS[1];
    }
    __syncthreads();
    float bM = Mall[0];
    #pragma unroll
    for (int j = 1; j < CS; j++) bM = fmaxf(bM, Mall[j]);
    float Z = 0.f;
    #pragma unroll
    for (int j = 0; j < CS; j++) Z += __expf(Mall[j] - bM) * Sall[j];
    float invZ = 1.0f / Z;

    if (t < 128)
        attn[b * Nn + rowC + t] = __expf(shAgg[t] - bM) * invZ;

    if (t < 128) {
        float y = 0.f;
        #pragma unroll
        for (int r = 0; r < CS; r++) {
            const float* pa = (const float*)cluster.map_shared_rank(shAcc, r);
            y += __expf(Mall[r] - bM) * pa[t];
        }
        shY[t] = y * invZ;
    }
    __syncthreads();
    cluster.sync();                       // #4: peers' smem alive until here

    // ---- ctx slice: 16 outputs per block, from local shY + sWv ---------------
    {
        int d = t & 15, seg = t >> 4;
        float a = 0.f;
        #pragma unroll
        for (int j = 0; j < 8; j++) {
            int f = seg * 8 + j;
            a += shY[f] * sWv[f * 17 + d];
        }
        prt[seg][d] = a;
    }
    __syncthreads();
    if (t < 16) {
        float a = 0.f;
        #pragma unroll
        for (int s = 0; s < 16; s++) a += prt[s][t];
        ctx[b * Dn + dBase + t] = shBv[t] + a;
    }
}

// ---------------------------------------------------------------------------
extern "C" void kernel_launch(void* const* d_in, const int* in_sizes, int n_in,
                              void* d_out, int out_size) {
    const float* X    = (const float*)d_in[0];
    const float* mask = (const float*)d_in[1];
    const float* Wq   = (const float*)d_in[2];
    const float* bq   = (const float*)d_in[3];
    const float* Wk   = (const float*)d_in[4];
    const float* bk   = (const float*)d_in[5];
    const float* Wv   = (const float*)d_in[6];
    const float* bv   = (const float*)d_in[7];
    float* out  = (float*)d_out;
    float* attn = out;              // [B,N,1]
    float* ctx  = out + Bn * Nn;    // [B,D]

    const int smemBytes = (Fn * Fn + 3 * Fn * 17) * (int)sizeof(float); // 91648
    static bool attrSet = false;
    if (!attrSet) {
        cudaFuncSetAttribute(ga, cudaFuncAttributeMaxDynamicSharedMemorySize, smemBytes);
        attrSet = true;
    }

    ga<<<Bn * CS, 256, smemBytes>>>(X, mask, Wq, bq, Wk, bk, Wv, bv, attn, ctx);
}